// round 15
// baseline (speedup 1.0000x reference)
#include <cuda_runtime.h>
#include <math.h>

#define T_DATA 20000
#define SUB 16
#define TNO 200
#define ENO 2000
#define INO 500
#define CHUNK 32
#define NCHUNK (T_DATA / CHUNK)
#define KSTR 17
#define KNIB_BYTES (4 * 256 * KSTR * 4)
#define PI_F 3.14159265358979323846f

// ---------------- device scratch (no allocs allowed) ----------------
__device__ float g_syn_e[T_DATA * SUB];
__device__ float g_syn_i[T_DATA * SUB];
__device__ float g_base[T_DATA * SUB];
__device__ float g_ekT[TNO * SUB];
__device__ float g_ikT[TNO * SUB];
__device__ float g_hkT[TNO * SUB];
__device__ unsigned char g_seg_e[ENO];
__device__ unsigned char g_seg_i[INO];
__device__ float g_cw[SUB * SUB];
__device__ float g_rho[SUB];
__device__ int   g_fast;

#define PAIR_BAR(id) asm volatile("bar.sync %0, %1;" :: "r"(id), "r"(64) : "memory")
#define TAIL_BAR()   asm volatile("bar.sync 4, 416;" ::: "memory")

// ---------------- K0: setup ----------------
__global__ void k_setup(const float* C_den, const float* C_syn_e, const float* C_syn_i,
                        const float* Tau_e, const float* Tau_i,
                        const float* W_e, const float* W_i,
                        const float* D_e, const float* D_i,
                        const float* Tau_spk, const float* W_spk,
                        const float* W_hist, float* out_filters)
{
    int tid = threadIdx.x;
    for (int idx = tid; idx < SUB * TNO; idx += blockDim.x) {
        int s = idx / TNO, j = idx % TNO;
        float t = (float)j;
        float te  = fmaxf(t - expf(D_e[s]), 0.f);
        float tte = te / expf(Tau_e[s]);
        float ek  = tte * expf(-tte) * expf(W_e[s]);
        float ti  = fmaxf(t - expf(D_i[s]), 0.f);
        float tti = ti / expf(Tau_i[s]);
        float ik  = -tti * expf(-tti) * expf(W_i[s]);
        float tts = t / expf(Tau_spk[s]);
        float sk  = tts * expf(-tts) * expf(W_spk[s]);
        float raw = 4.0f * logf(t + 1.0f);
        float hk = 0.f;
        for (int b = 0; b < 16; b++) {
            float phi = PI_F * 0.5f * (float)b;
            float v = 0.f;
            if (!(raw < phi - PI_F || raw > phi + PI_F))
                v = 0.5f * cosf(raw - phi) + 0.5f;
            hk += W_hist[s * 16 + b] * v;
        }
        g_ekT[j * SUB + s] = ek;
        g_ikT[j * SUB + s] = ik;
        g_hkT[j * SUB + s] = hk;
        out_filters[(0  + s) * TNO + j] = ek;
        out_filters[(16 + s) * TNO + j] = ik;
        out_filters[(32 + s) * TNO + j] = sk;
        out_filters[(48 + s) * TNO + j] = hk;
    }
    for (int e = tid; e < ENO; e += blockDim.x) {
        int seg = 0;
        for (int s = 0; s < SUB; s++) if (C_syn_e[s * ENO + e] > 0.5f) seg = s;
        g_seg_e[e] = (unsigned char)seg;
    }
    for (int e = tid; e < INO; e += blockDim.x) {
        int seg = 0;
        for (int s = 0; s < SUB; s++) if (C_syn_i[s * INO + e] > 0.5f) seg = s;
        g_seg_i[e] = (unsigned char)seg;
    }
    if (tid < SUB) g_rho[tid] = expf(-1.0f / expf(Tau_spk[tid]));
    if (tid < SUB * SUB) {
        int s = tid >> 4, q = tid & 15;
        g_cw[s * SUB + q] = C_den[s * SUB + q] * expf(W_spk[q]) / expf(Tau_spk[q]);
    }
    __syncthreads();
    if (tid == 0) {
        int fast = 1;
        float r0 = g_rho[0];
        for (int s = 1; s < SUB; s++) if (g_rho[s] != r0) fast = 0;
        g_fast = fast;
    }
}

// ---------------- K1: segment sums ----------------
#define SEG_ROWS 4
__global__ void k_segsum(const float* __restrict__ S_e, const float* __restrict__ S_i)
{
    __shared__ unsigned char sege[ENO];
    __shared__ unsigned char segi[INO];
    __shared__ float acc[SEG_ROWS][32];
    int tid = threadIdx.x;
    for (int e = tid; e < ENO; e += blockDim.x) sege[e] = g_seg_e[e];
    for (int e = tid; e < INO; e += blockDim.x) segi[e] = g_seg_i[e];
    if (tid < SEG_ROWS * 32) ((float*)acc)[tid] = 0.f;
    __syncthreads();
    int t0 = blockIdx.x * SEG_ROWS;
    for (int r = 0; r < SEG_ROWS; r++) {
        const float* re = S_e + (size_t)(t0 + r) * ENO;
        for (int e = tid; e < ENO; e += blockDim.x) {
            float v = re[e];
            if (v != 0.f) atomicAdd(&acc[r][sege[e]], v);
        }
        const float* ri = S_i + (size_t)(t0 + r) * INO;
        for (int e = tid; e < INO; e += blockDim.x) {
            float v = ri[e];
            if (v != 0.f) atomicAdd(&acc[r][16 + segi[e]], v);
        }
    }
    __syncthreads();
    if (tid < SEG_ROWS * 32) {
        int r = tid >> 5, q = tid & 31;
        if (q < 16) g_syn_e[(t0 + r) * SUB + q] = acc[r][q];
        else        g_syn_i[(t0 + r) * SUB + (q - 16)] = acc[r][q];
    }
}

// ---------------- K2: causal depthwise FIR + Theta -> base ----------------
#define TILE_T 128
__global__ void k_conv(const float* __restrict__ Theta)
{
    __shared__ float se[(TILE_T + TNO) * SUB];
    __shared__ float si[(TILE_T + TNO) * SUB];
    int t0 = blockIdx.x * TILE_T;
    int tid = threadIdx.x;
    for (int idx = tid; idx < 327 * SUB; idx += blockDim.x) {
        int r = idx / SUB, s = idx % SUB;
        int tt = t0 - 200 + r;
        float ve = 0.f, vi = 0.f;
        if (tt >= 0 && tt < T_DATA) {
            ve = g_syn_e[tt * SUB + s];
            vi = g_syn_i[tt * SUB + s];
        }
        se[idx] = ve;
        si[idx] = vi;
    }
    __syncthreads();
    int s = tid & 15, tg = tid >> 4;
    float th = Theta[s];
    float acc[8];
#pragma unroll
    for (int k = 0; k < 8; k++) acc[k] = th;
    for (int j = 0; j < TNO; j++) {
        float ke = g_ekT[j * SUB + s];
        float ki = g_ikT[j * SUB + s];
#pragma unroll
        for (int k = 0; k < 8; k++) {
            int tl = tg + k * 16;
            int row = tl + 199 - j;
            acc[k] += ke * se[row * SUB + s] + ki * si[row * SUB + s];
        }
    }
#pragma unroll
    for (int k = 0; k < 8; k++) {
        int t = t0 + tg + k * 16;
        if (t < T_DATA) g_base[t * SUB + s] = acc[k];
    }
}

// ---------------- K3: chain (wid 0-3) + tail word-c pass; applies via knib ----------------
__global__ void __launch_bounds__(512, 1) k_scan(float* __restrict__ spk_out)
{
    extern __shared__ float knib[];         // [state][d][s] stride 17: b0*k[d]+b1*k[d-1]
    __shared__ float kpad[256 * KSTR];
    __shared__ unsigned ring[16 * SUB];
    __shared__ float inj_sh[CHUNK * SUB];
    __shared__ unsigned balw[2][4][4];      // [buf][round][phase] ballots (A | B<<16)
    __shared__ float lut[4][16][16];
    __shared__ float S2_sh[32 * KSTR];
    __shared__ float Pn_sh[2][32 * KSTR];
    __shared__ float cw_sh[SUB * 17];
    __shared__ float rho_sh[SUB];
    __shared__ float MA0[SUB], MB0[SUB];
    __shared__ float powt[CHUNK + 1], wt[CHUNK + 1];
    __shared__ int fast_sh;
    // fallback-only
    __shared__ float spf[CHUNK * SUB], P_sh[CHUNK * SUB], base_sh[CHUNK * SUB];
    __shared__ float Kpre_sh[32 * KSTR];

    int tid = threadIdx.x;
    int wid = tid >> 5, lane = tid & 31;

    for (int idx = tid; idx < 256 * KSTR; idx += 512) kpad[idx] = 0.f;
    for (int idx = tid; idx < 2 * 32 * KSTR; idx += 512) ((float*)Pn_sh)[idx] = 0.f;
    if (tid < 32) ((unsigned*)balw)[tid] = 0u;
    if (tid < 256) {
        int s = tid >> 4, q = tid & 15;
        cw_sh[s * 17 + q] = g_cw[s * SUB + q];
        ring[tid] = 0u;
    }
    if (tid < SUB) {
        rho_sh[tid] = g_rho[tid];
        MA0[tid] = 0.f; MB0[tid] = 0.f;
    }
    if (tid == 0) fast_sh = g_fast;
    __syncthreads();
    for (int idx = tid; idx < TNO * SUB; idx += 512) {
        int j = idx >> 4, s = idx & 15;
        kpad[j * KSTR + s] = g_hkT[idx];
    }
    if (tid <= CHUNK) {
        float p = powf(rho_sh[0], (float)tid);
        powt[tid] = p;
        wt[tid] = (float)tid * p;
    }
    for (int idx = tid; idx < 1024; idx += 512) {
        int n = idx >> 8, m = (idx >> 4) & 15, ss = idx & 15;
        float v = 0.f;
        for (int b = 0; b < 4; b++)
            if ((m >> b) & 1) v += cw_sh[ss * 17 + 4 * n + b];
        lut[n][m][ss] = v;
    }
    __syncthreads();
    {
        int ii = tid >> 4, ss = tid & 15;
        float suf = 0.f;
        for (int b = ii + 32; b < TNO; b++) suf += kpad[b * KSTR + ss];
        S2_sh[ii * KSTR + ss] = suf;
        float pre = 0.f;
        for (int b = 0; b < ii; b++) pre += kpad[b * KSTR + ss];
        Kpre_sh[ii * KSTR + ss] = pre;
    }
    // 2-bit-pair LUT (needs kpad); knib[0][*] = 0
    for (int idx = tid; idx < 4 * 256 * 16; idx += 512) {
        int st = idx >> 12, d = (idx >> 4) & 255, s = idx & 15;
        float v = 0.f;
        if (st & 1) v += kpad[d * KSTR + s];
        if ((st & 2) && d >= 1) v += kpad[(d - 1) * KSTR + s];
        knib[(st * 256 + d) * KSTR + s] = v;
    }
    __syncthreads();

    // fallback state
    float MBr = 0.f, A = 0.f, B = 0.f;
    float cwrow[16];
    if (tid < 16) {
#pragma unroll
        for (int q = 0; q < 16; q++) cwrow[q] = cw_sh[tid * 17 + q];
    }
    const int fi = tid >> 4, fs = tid & 15;
    float fbase = g_base[fi * SUB + fs];

    // chain constants (wid 0..3)
    const int half = lane >> 4, sc = lane & 15;
    float kcr[7], wtr[7];
#pragma unroll
    for (int d = 0; d < 7; d++) { kcr[d] = kpad[d * KSTR + sc]; wtr[d] = wt[d]; }
    float p32 = powt[CHUNK];
    float invp32 = 1.f / p32;
    float base_r[4], powi[4], wti[4], rpw[4], ipm[4];
    if (wid < 4) {
#pragma unroll
        for (int p = 0; p < 4; p++) {
            int ip = 8 * wid + 2 * p + half;
            powi[p] = powt[ip];
            wti[p] = wt[ip];
            rpw[p] = powt[ip] * invp32;
            ipm[p] = (float)(ip - 32);
            base_r[p] = g_base[ip * SUB + sc];
        }
    }
    const int pns0 = (wid - 8) * 2, pns1 = pns0 + 1;   // Pn warps: wid 8..15

    for (int c = 0; c < NCHUNK; c++) {
        int t0 = c * CHUNK;

        if (fast_sh) {
            if (wid < 4) {
                // ---- prologue: bP only (word c-1 folded into Pn_sh by prior tail) ----
                float mb = MB0[sc], ma = MA0[sc];
                float bPv[4], acck[4];
#pragma unroll
                for (int p = 0; p < 4; p++) {
                    int ip = 8 * wid + 2 * p + half;
                    bPv[p] = base_r[p] + Pn_sh[c & 1][ip * KSTR + sc] + powi[p] * mb + wti[p] * ma;
                    acck[p] = 0.f;
                }
                float Qa = 0.f, Qb = 0.f;
                if (wid == 0) {
                    if (half == 0) ring[(c & 15) * SUB + sc] = 0u;
                } else {
                    PAIR_BAR(wid);
                    const unsigned (*bc)[4] = balw[c & 1];
#pragma unroll
                    for (int r = 0; r < 3; r++) if (r < wid) {
#pragma unroll
                        for (int ph = 0; ph < 4; ph++) {
                            unsigned bw = bc[r][ph];
                            int ue = 8 * r + 2 * ph;
                            float je = inj_sh[ue * SUB + sc];
                            float jo = inj_sh[(ue + 1) * SUB + sc];
                            Qa += powt[31 - ue] * je + powt[30 - ue] * jo;
                            Qb += wt[31 - ue] * je + wt[30 - ue] * jo;
                            unsigned st = ((bw >> sc) & 1u) | (((bw >> (16 + sc)) & 1u) << 1);
                            const float* kn = knib + (st * 256) * KSTR + sc;
#pragma unroll
                            for (int p = 0; p < 4; p++) {
                                int de = (8 * wid + 2 * p + half) - 1 - ue;
                                acck[p] += kn[de * KSTR];
                            }
                        }
                    }
                }
                // ---- 4 in-warp phases (8 steps), parallel hypothesis ballots ----
                unsigned balAv[4], balBv[4];
                float injE[4];
                float inw[4] = {0.f, 0.f, 0.f, 0.f};
#pragma unroll
                for (int p = 0; p < 4; p++) {
                    float sub = bPv[p] + acck[p] + inw[p] + rpw[p] * (ipm[p] * Qa + Qb);
                    unsigned b1 = __ballot_sync(0xFFFFFFFFu, sub > 0.f);
                    unsigned b2 = __ballot_sync(0xFFFFFFFFu, sub + kcr[0] > 0.f);
                    unsigned balA = b1 & 0xFFFFu;
                    unsigned h0 = b1 >> 16, h1 = b2 >> 16;
                    unsigned balB = (balA & h1) | (~balA & h0);
                    balAv[p] = balA; balBv[p] = balB;
                    float injEv = lut[0][balA & 15][sc] + lut[1][(balA >> 4) & 15][sc]
                                + lut[2][(balA >> 8) & 15][sc] + lut[3][(balA >> 12) & 15][sc];
                    float injOd = lut[0][balB & 15][sc] + lut[1][(balB >> 4) & 15][sc]
                                + lut[2][(balB >> 8) & 15][sc] + lut[3][(balB >> 12) & 15][sc];
                    injE[p] = half ? injOd : injEv;
                    if (p < 3) {
                        float fe = (float)((balA >> sc) & 1u);
                        float fo = (float)((balB >> sc) & 1u);
#pragma unroll
                        for (int pp = p + 1; pp < 4; pp++) {
                            const int bd = 2 * (pp - p) - 1;   // 1,3,5
                            float kA = half ? kcr[bd + 1] : kcr[bd];
                            float kB = half ? kcr[bd] : kcr[bd - 1];
                            float wA = half ? wtr[bd + 1] : wtr[bd];
                            float wB = half ? wtr[bd] : wtr[bd - 1];
                            inw[pp] += fe * kA + wA * injEv + fo * kB + wB * injOd;
                        }
                    }
                }
                // ---- publish + ring bits (pre-release, bar-ordered for tail) ----
#pragma unroll
                for (int p = 0; p < 4; p++)
                    inj_sh[(8 * wid + 2 * p + half) * SUB + sc] = injE[p];
                if (lane == 0) {
                    balw[c & 1][wid][0] = balAv[0] | (balBv[0] << 16);
                    balw[c & 1][wid][1] = balAv[1] | (balBv[1] << 16);
                    balw[c & 1][wid][2] = balAv[2] | (balBv[2] << 16);
                    balw[c & 1][wid][3] = balAv[3] | (balBv[3] << 16);
                }
                if (half == 0) {
                    unsigned bits = 0u;
#pragma unroll
                    for (int p = 0; p < 4; p++)
                        bits |= (((balAv[p] >> sc) & 1u) << (8 * wid + 2 * p))
                              | (((balBv[p] >> sc) & 1u) << (8 * wid + 2 * p + 1));
                    atomicOr(&ring[(c & 15) * SUB + sc], bits);
                }
                if (wid < 3) PAIR_BAR(wid + 1); else TAIL_BAR();
                // ---- post-release ----
#pragma unroll
                for (int p = 0; p < 4; p++) {
                    unsigned myb = half ? balBv[p] : balAv[p];
                    spk_out[(t0 + 8 * wid + 2 * p + half) * SUB + sc] = ((myb >> sc) & 1u) ? 1.f : 0.f;
                }
                if (c + 1 < NCHUNK) {
#pragma unroll
                    for (int p = 0; p < 4; p++)
                        base_r[p] = g_base[(t0 + CHUNK + 8 * wid + 2 * p + half) * SUB + sc];
                }
            } else if (wid == 4) {
                // ---- epilogue: MA0/MB0 closed-form update ----
                TAIL_BAR();
                float sAp = 0.f, sBp = 0.f;
                int u0 = half * 16;
#pragma unroll
                for (int u = 0; u < 16; u++) {
                    float v = inj_sh[(u0 + u) * SUB + sc];
                    sAp += powt[31 - (u0 + u)] * v;
                    sBp += wt[31 - (u0 + u)] * v;
                }
                float sA = sAp + __shfl_xor_sync(0xFFFFFFFFu, sAp, 16);
                float sB = sBp + __shfl_xor_sync(0xFFFFFFFFu, sBp, 16);
                if (half == 0) {
                    float oMA = MA0[sc], oMB = MB0[sc];
                    MA0[sc] = p32 * oMA + sA;
                    MB0[sc] = p32 * oMB + 32.f * p32 * oMA + sB;
                }
            } else if (wid < 8) {
                // ---- tail producers (idle during chunk): word-c add into Pn_sh ----
                TAIL_BAR();
                if (c + 1 < NCHUNK) {
#pragma unroll
                    for (int pass = 0; pass < 2; pass++) {
                        int s = (pass == 0) ? (wid - 5) : (wid + 6);   // wid 5..7 -> s 0..2, 11..13
                        unsigned W = ring[(c & 15) * SUB + s];
                        float add = 0.f;
                        int D0 = 31 + lane;
#pragma unroll
                        for (int jp = 0; jp < 16; jp++) {
                            unsigned st = (W >> (2 * jp)) & 3u;
                            if (st) add += knib[(st * 256 + (D0 - 2 * jp)) * KSTR + s];
                        }
                        Pn_sh[(c + 1) & 1][lane * KSTR + s] += add;
                    }
                }
            } else {
                // ---- Pn warps: words c-6..c-1 during chunk, then tail word-c pass ----
                if (c + 1 < NCHUNK) {
                    int wbase = c - 6;
#pragma unroll
                    for (int pass = 0; pass < 2; pass++) {
                        int s = pass ? pns1 : pns0;
                        unsigned W[6];
                        int ones = 0;
#pragma unroll
                        for (int q = 0; q < 6; q++) {
                            int w = wbase + q;
                            unsigned wd = (w >= 0) ? ring[(w & 15) * SUB + s] : 0u;
                            W[q] = wd;
                            ones += __popc(wd);
                        }
                        float Pv;
                        if (ones >= 168) {
                            float a0 = 0.f, a1 = 0.f;
#pragma unroll
                            for (int q = 0; q < 6; q++) {
                                unsigned zm = ~W[q];
                                int D0 = 223 - 32 * q + lane;
                                while (zm) {
                                    int b = __ffs(zm) - 1; zm &= zm - 1u;
                                    a0 += kpad[(D0 - b) * KSTR + s];
                                    if (zm) {
                                        b = __ffs(zm) - 1; zm &= zm - 1u;
                                        a1 += kpad[(D0 - b) * KSTR + s];
                                    }
                                }
                            }
                            Pv = S2_sh[lane * KSTR + s] - a0 - a1;
                        } else if (ones <= 24) {
                            float a0 = 0.f, a1 = 0.f;
#pragma unroll
                            for (int q = 0; q < 6; q++) {
                                unsigned om = W[q];
                                int D0 = 223 - 32 * q + lane;
                                while (om) {
                                    int b = __ffs(om) - 1; om &= om - 1u;
                                    a0 += kpad[(D0 - b) * KSTR + s];
                                    if (om) {
                                        b = __ffs(om) - 1; om &= om - 1u;
                                        a1 += kpad[(D0 - b) * KSTR + s];
                                    }
                                }
                            }
                            Pv = a0 + a1;
                        } else {
                            float a0 = 0.f, a1 = 0.f;
#pragma unroll
                            for (int q = 0; q < 6; q++) {
                                unsigned Wq = W[q];
                                int D0 = 223 - 32 * q + lane;
#pragma unroll
                                for (int jp = 0; jp < 16; jp += 2) {
                                    unsigned st0 = (Wq >> (2 * jp)) & 3u;
                                    unsigned st1 = (Wq >> (2 * jp + 2)) & 3u;
                                    if (st0) a0 += knib[(st0 * 256 + (D0 - 2 * jp)) * KSTR + s];
                                    if (st1) a1 += knib[(st1 * 256 + (D0 - 2 * jp - 2)) * KSTR + s];
                                }
                            }
                            Pv = a0 + a1;
                        }
                        Pn_sh[(c + 1) & 1][lane * KSTR + s] = Pv;
                    }
                }
                TAIL_BAR();
                if (c + 1 < NCHUNK) {
                    int s = wid - 5;                      // wid 8..15 -> s 3..10
                    unsigned W = ring[(c & 15) * SUB + s];
                    float add = 0.f;
                    int D0 = 31 + lane;
#pragma unroll
                    for (int jp = 0; jp < 16; jp++) {
                        unsigned st = (W >> (2 * jp)) & 3u;
                        if (st) add += knib[(st * 256 + (D0 - 2 * jp)) * KSTR + s];
                    }
                    Pn_sh[(c + 1) & 1][lane * KSTR + s] += add;
                    if (wid >= 13) {                      // wid 13..15 -> s 14,15 + spare
                        int s2 = wid + 1;                 // 14,15,16(skip)
                        if (s2 < 16) {
                            unsigned W2 = ring[(c & 15) * SUB + s2];
                            float add2 = 0.f;
#pragma unroll
                            for (int jp = 0; jp < 16; jp++) {
                                unsigned st = (W2 >> (2 * jp)) & 3u;
                                if (st) add2 += knib[(st * 256 + (D0 - 2 * jp)) * KSTR + s2];
                            }
                            Pn_sh[(c + 1) & 1][lane * KSTR + s2] += add2;
                        }
                    }
                }
            }
            __syncthreads();
        } else {
            // ---- general fallback: per-thread pre-phase + serial loop ----
            float P = 0.f;
            {
                int t = t0 + fi;
                int uhi = t0 - 1;
                int ulo = t - TNO; if (ulo < 0) ulo = 0;
                if (uhi >= ulo) {
                    int wlo = ulo >> 5;
#pragma unroll
                    for (int q8 = 0; q8 < 8; q8++) {
                        int w = wlo + q8;
                        int bu = w << 5;
                        unsigned valid = 0u;
                        if (bu >= 0 && bu <= uhi) {
                            valid = 0xFFFFFFFFu;
                            if (bu < ulo) valid <<= (ulo - bu);
                            int hb = uhi - bu;
                            if (hb < 31) valid &= ((2u << hb) - 1u);
                        }
                        unsigned om = (valid ? ring[(w & 15) * SUB + fs] : 0u) & valid;
                        int Cw = t - 1 - (w << 5);
                        while (om) {
                            int b = __ffs(om) - 1; om &= om - 1u;
                            P += kpad[(Cw - b) * KSTR + fs];
                        }
                    }
                }
            }
            P_sh[tid] = P;
            base_sh[tid] = fbase;
            __syncthreads();
            if (tid < 16) {
                int ss = tid;
                unsigned myhist = 0u;
                float rho_s = rho_sh[ss];
                for (int ii = 0; ii < CHUNK; ii++) {
                    float Pv2 = P_sh[ii * SUB + ss];
                    float bv = base_sh[ii * SUB + ss];
                    unsigned m = ii ? ((1u << ii) - 1u) : 0u;
                    unsigned om = myhist & m;
                    float intra;
                    if (2 * __popc(om) > ii) {
                        unsigned zm = om ^ m;
                        float a = 0.f;
                        while (zm) { int b = __ffs(zm) - 1; zm &= zm - 1u; a += kpad[b * KSTR + ss]; }
                        intra = Kpre_sh[ii * KSTR + ss] - a;
                    } else {
                        float a = 0.f;
                        while (om) { int b = __ffs(om) - 1; om &= om - 1u; a += kpad[b * KSTR + ss]; }
                        intra = a;
                    }
                    float sub = bv + Pv2 + intra + MBr;
                    bool sp = sub > 0.f;
                    spf[ii * SUB + ss] = sp ? 1.f : 0.f;
                    myhist = (myhist << 1) | (sp ? 1u : 0u);
                    float Ao = A;
                    B = rho_s * (B + Ao);
                    A = rho_s * Ao + (sp ? 1.f : 0.f);
                    float accv = 0.f;
#pragma unroll
                    for (int q = 0; q < 16; q++)
                        accv += cwrow[q] * __shfl_sync(0x0000FFFFu, B, q);
                    MBr = accv;
                }
                ring[((t0 >> 5) & 15) * SUB + ss] = __brev(myhist);
            }
            __syncthreads();
            spk_out[t0 * SUB + tid] = spf[tid];
            float nextbase = 0.f;
            if (c + 1 < NCHUNK) nextbase = g_base[(t0 + CHUNK + fi) * SUB + fs];
            __syncthreads();
            fbase = nextbase;
        }
    }
}

// ---------------- launch ----------------
extern "C" void kernel_launch(void* const* d_in, const int* in_sizes, int n_in,
                              void* d_out, int out_size)
{
    const float* S_e     = (const float*)d_in[0];
    const float* S_i     = (const float*)d_in[1];
    const float* C_den   = (const float*)d_in[2];
    const float* C_syn_e = (const float*)d_in[3];
    const float* C_syn_i = (const float*)d_in[4];
    const float* Tau_e   = (const float*)d_in[5];
    const float* Tau_i   = (const float*)d_in[6];
    const float* W_e     = (const float*)d_in[7];
    const float* W_i     = (const float*)d_in[8];
    const float* D_e     = (const float*)d_in[9];
    const float* D_i     = (const float*)d_in[10];
    const float* Tau_spk = (const float*)d_in[11];
    const float* W_spk   = (const float*)d_in[12];
    const float* W_hist  = (const float*)d_in[13];
    const float* Theta   = (const float*)d_in[14];
    float* out = (float*)d_out;
    float* out_filters = out + T_DATA * SUB;

    cudaFuncSetAttribute(k_scan, cudaFuncAttributeMaxDynamicSharedMemorySize, KNIB_BYTES);

    k_setup<<<1, 256>>>(C_den, C_syn_e, C_syn_i, Tau_e, Tau_i, W_e, W_i,
                        D_e, D_i, Tau_spk, W_spk, W_hist, out_filters);
    k_segsum<<<T_DATA / SEG_ROWS, 256>>>(S_e, S_i);
    k_conv<<<(T_DATA + TILE_T - 1) / TILE_T, 256>>>(Theta);
    k_scan<<<1, 512, KNIB_BYTES>>>(out);
}

// round 16
// speedup vs baseline: 1.7193x; 1.7193x over previous
#include <cuda_runtime.h>
#include <math.h>

#define T_DATA 20000
#define SUB 16
#define TNO 200
#define ENO 2000
#define INO 500
#define CHUNK 32
#define NCHUNK (T_DATA / CHUNK)
#define KSTR 17
#define KNIB_BYTES (4 * 256 * KSTR * 4)
#define PI_F 3.14159265358979323846f

// ---------------- device scratch (no allocs allowed) ----------------
__device__ float g_syn_e[T_DATA * SUB];
__device__ float g_syn_i[T_DATA * SUB];
__device__ float g_base[T_DATA * SUB];
__device__ float g_ekT[TNO * SUB];
__device__ float g_ikT[TNO * SUB];
__device__ float g_hkT[TNO * SUB];
__device__ unsigned char g_seg_e[ENO];
__device__ unsigned char g_seg_i[INO];
__device__ float g_cw[SUB * SUB];
__device__ float g_rho[SUB];
__device__ int   g_fast;

#define PAIR_BAR(id) asm volatile("bar.sync %0, %1;" :: "r"(id), "r"(64) : "memory")

// ---------------- K0: setup ----------------
__global__ void k_setup(const float* C_den, const float* C_syn_e, const float* C_syn_i,
                        const float* Tau_e, const float* Tau_i,
                        const float* W_e, const float* W_i,
                        const float* D_e, const float* D_i,
                        const float* Tau_spk, const float* W_spk,
                        const float* W_hist, float* out_filters)
{
    int tid = threadIdx.x;
    for (int idx = tid; idx < SUB * TNO; idx += blockDim.x) {
        int s = idx / TNO, j = idx % TNO;
        float t = (float)j;
        float te  = fmaxf(t - expf(D_e[s]), 0.f);
        float tte = te / expf(Tau_e[s]);
        float ek  = tte * expf(-tte) * expf(W_e[s]);
        float ti  = fmaxf(t - expf(D_i[s]), 0.f);
        float tti = ti / expf(Tau_i[s]);
        float ik  = -tti * expf(-tti) * expf(W_i[s]);
        float tts = t / expf(Tau_spk[s]);
        float sk  = tts * expf(-tts) * expf(W_spk[s]);
        float raw = 4.0f * logf(t + 1.0f);
        float hk = 0.f;
        for (int b = 0; b < 16; b++) {
            float phi = PI_F * 0.5f * (float)b;
            float v = 0.f;
            if (!(raw < phi - PI_F || raw > phi + PI_F))
                v = 0.5f * cosf(raw - phi) + 0.5f;
            hk += W_hist[s * 16 + b] * v;
        }
        g_ekT[j * SUB + s] = ek;
        g_ikT[j * SUB + s] = ik;
        g_hkT[j * SUB + s] = hk;
        out_filters[(0  + s) * TNO + j] = ek;
        out_filters[(16 + s) * TNO + j] = ik;
        out_filters[(32 + s) * TNO + j] = sk;
        out_filters[(48 + s) * TNO + j] = hk;
    }
    for (int e = tid; e < ENO; e += blockDim.x) {
        int seg = 0;
        for (int s = 0; s < SUB; s++) if (C_syn_e[s * ENO + e] > 0.5f) seg = s;
        g_seg_e[e] = (unsigned char)seg;
    }
    for (int e = tid; e < INO; e += blockDim.x) {
        int seg = 0;
        for (int s = 0; s < SUB; s++) if (C_syn_i[s * INO + e] > 0.5f) seg = s;
        g_seg_i[e] = (unsigned char)seg;
    }
    if (tid < SUB) g_rho[tid] = expf(-1.0f / expf(Tau_spk[tid]));
    if (tid < SUB * SUB) {
        int s = tid >> 4, q = tid & 15;
        g_cw[s * SUB + q] = C_den[s * SUB + q] * expf(W_spk[q]) / expf(Tau_spk[q]);
    }
    __syncthreads();
    if (tid == 0) {
        int fast = 1;
        float r0 = g_rho[0];
        for (int s = 1; s < SUB; s++) if (g_rho[s] != r0) fast = 0;
        g_fast = fast;
    }
}

// ---------------- K1: segment sums ----------------
#define SEG_ROWS 4
__global__ void k_segsum(const float* __restrict__ S_e, const float* __restrict__ S_i)
{
    __shared__ unsigned char sege[ENO];
    __shared__ unsigned char segi[INO];
    __shared__ float acc[SEG_ROWS][32];
    int tid = threadIdx.x;
    for (int e = tid; e < ENO; e += blockDim.x) sege[e] = g_seg_e[e];
    for (int e = tid; e < INO; e += blockDim.x) segi[e] = g_seg_i[e];
    if (tid < SEG_ROWS * 32) ((float*)acc)[tid] = 0.f;
    __syncthreads();
    int t0 = blockIdx.x * SEG_ROWS;
    for (int r = 0; r < SEG_ROWS; r++) {
        const float* re = S_e + (size_t)(t0 + r) * ENO;
        for (int e = tid; e < ENO; e += blockDim.x) {
            float v = re[e];
            if (v != 0.f) atomicAdd(&acc[r][sege[e]], v);
        }
        const float* ri = S_i + (size_t)(t0 + r) * INO;
        for (int e = tid; e < INO; e += blockDim.x) {
            float v = ri[e];
            if (v != 0.f) atomicAdd(&acc[r][16 + segi[e]], v);
        }
    }
    __syncthreads();
    if (tid < SEG_ROWS * 32) {
        int r = tid >> 5, q = tid & 31;
        if (q < 16) g_syn_e[(t0 + r) * SUB + q] = acc[r][q];
        else        g_syn_i[(t0 + r) * SUB + (q - 16)] = acc[r][q];
    }
}

// ---------------- K2: causal depthwise FIR + Theta -> base ----------------
#define TILE_T 128
__global__ void k_conv(const float* __restrict__ Theta)
{
    __shared__ float se[(TILE_T + TNO) * SUB];
    __shared__ float si[(TILE_T + TNO) * SUB];
    int t0 = blockIdx.x * TILE_T;
    int tid = threadIdx.x;
    for (int idx = tid; idx < 327 * SUB; idx += blockDim.x) {
        int r = idx / SUB, s = idx % SUB;
        int tt = t0 - 200 + r;
        float ve = 0.f, vi = 0.f;
        if (tt >= 0 && tt < T_DATA) {
            ve = g_syn_e[tt * SUB + s];
            vi = g_syn_i[tt * SUB + s];
        }
        se[idx] = ve;
        si[idx] = vi;
    }
    __syncthreads();
    int s = tid & 15, tg = tid >> 4;
    float th = Theta[s];
    float acc[8];
#pragma unroll
    for (int k = 0; k < 8; k++) acc[k] = th;
    for (int j = 0; j < TNO; j++) {
        float ke = g_ekT[j * SUB + s];
        float ki = g_ikT[j * SUB + s];
#pragma unroll
        for (int k = 0; k < 8; k++) {
            int tl = tg + k * 16;
            int row = tl + 199 - j;
            acc[k] += ke * se[row * SUB + s] + ki * si[row * SUB + s];
        }
    }
#pragma unroll
    for (int k = 0; k < 8; k++) {
        int t = t0 + tg + k * 16;
        if (t < T_DATA) g_base[t * SUB + s] = acc[k];
    }
}

// ---------------- K3: R13 structure + knib-compressed chain applies ----------------
__global__ void __launch_bounds__(512, 1) k_scan(float* __restrict__ spk_out)
{
    extern __shared__ float knib[];         // [state][d][s] stride 17: b0*k[d]+b1*k[d-1]
    __shared__ float kpad[256 * KSTR];
    __shared__ unsigned ring[16 * SUB];
    __shared__ float inj_sh[CHUNK * SUB];
    __shared__ unsigned balw[2][4][4];      // [buf][round][phase] ballots (A | B<<16)
    __shared__ float lut[4][16][16];
    __shared__ float S2_sh[32 * KSTR];
    __shared__ float Pn_sh[2][32 * KSTR];
    __shared__ float cw_sh[SUB * 17];
    __shared__ float rho_sh[SUB];
    __shared__ float MA0[SUB], MB0[SUB];
    __shared__ float powt[CHUNK + 1], wt[CHUNK + 1];
    __shared__ int fast_sh;
    // fallback-only
    __shared__ float spf[CHUNK * SUB], P_sh[CHUNK * SUB], base_sh[CHUNK * SUB];
    __shared__ float Kpre_sh[32 * KSTR];

    int tid = threadIdx.x;
    int wid = tid >> 5, lane = tid & 31;

    for (int idx = tid; idx < 256 * KSTR; idx += 512) kpad[idx] = 0.f;
    for (int idx = tid; idx < 2 * 32 * KSTR; idx += 512) ((float*)Pn_sh)[idx] = 0.f;
    if (tid < 32) ((unsigned*)balw)[tid] = 0u;
    if (tid < 256) {
        int s = tid >> 4, q = tid & 15;
        cw_sh[s * 17 + q] = g_cw[s * SUB + q];
        ring[tid] = 0u;
    }
    if (tid < SUB) {
        rho_sh[tid] = g_rho[tid];
        MA0[tid] = 0.f; MB0[tid] = 0.f;
    }
    if (tid == 0) fast_sh = g_fast;
    __syncthreads();
    for (int idx = tid; idx < TNO * SUB; idx += 512) {
        int j = idx >> 4, s = idx & 15;
        kpad[j * KSTR + s] = g_hkT[idx];
    }
    if (tid <= CHUNK) {
        float p = powf(rho_sh[0], (float)tid);
        powt[tid] = p;
        wt[tid] = (float)tid * p;
    }
    for (int idx = tid; idx < 1024; idx += 512) {
        int n = idx >> 8, m = (idx >> 4) & 15, ss = idx & 15;
        float v = 0.f;
        for (int b = 0; b < 4; b++)
            if ((m >> b) & 1) v += cw_sh[ss * 17 + 4 * n + b];
        lut[n][m][ss] = v;
    }
    __syncthreads();
    {
        int ii = tid >> 4, ss = tid & 15;
        float suf = 0.f;
        for (int b = ii + 32; b < TNO; b++) suf += kpad[b * KSTR + ss];
        S2_sh[ii * KSTR + ss] = suf;
        float pre = 0.f;
        for (int b = 0; b < ii; b++) pre += kpad[b * KSTR + ss];
        Kpre_sh[ii * KSTR + ss] = pre;
    }
    // 2-bit-pair LUT (needs kpad); knib[0][*] = 0
    for (int idx = tid; idx < 4 * 256 * 16; idx += 512) {
        int st = idx >> 12, d = (idx >> 4) & 255, s = idx & 15;
        float v = 0.f;
        if (st & 1) v += kpad[d * KSTR + s];
        if ((st & 2) && d >= 1) v += kpad[(d - 1) * KSTR + s];
        knib[(st * 256 + d) * KSTR + s] = v;
    }
    __syncthreads();

    // fallback state
    float MBr = 0.f, A = 0.f, B = 0.f;
    float cwrow[16];
    if (tid < 16) {
#pragma unroll
        for (int q = 0; q < 16; q++) cwrow[q] = cw_sh[tid * 17 + q];
    }
    const int fi = tid >> 4, fs = tid & 15;
    float fbase = g_base[fi * SUB + fs];

    // chain constants (wid 0..3)
    const int half = lane >> 4, sc = lane & 15;
    float kcr[7], wtr[7];
#pragma unroll
    for (int d = 0; d < 7; d++) { kcr[d] = kpad[d * KSTR + sc]; wtr[d] = wt[d]; }
    float p32 = powt[CHUNK];
    float invp32 = 1.f / p32;
    float base_r[4], powi[4], wti[4], rpw[4], ipm[4];
    if (wid < 4) {
#pragma unroll
        for (int p = 0; p < 4; p++) {
            int ip = 8 * wid + 2 * p + half;
            powi[p] = powt[ip];
            wti[p] = wt[ip];
            rpw[p] = powt[ip] * invp32;
            ipm[p] = (float)(ip - 32);
            base_r[p] = g_base[ip * SUB + sc];
        }
    }
    const int pns0 = (wid - 8) * 2, pns1 = pns0 + 1;   // Pn warps: wid 8..15

    for (int c = 0; c < NCHUNK; c++) {
        int t0 = c * CHUNK;

        if (fast_sh) {
            if (wid < 4) {
                // ---- prologue: bP + prev-chunk k applies via knib ----
                float mb = MB0[sc], ma = MA0[sc];
                float bPv[4], acck[4];
#pragma unroll
                for (int p = 0; p < 4; p++) {
                    int ip = 8 * wid + 2 * p + half;
                    bPv[p] = base_r[p] + Pn_sh[c & 1][ip * KSTR + sc] + powi[p] * mb + wti[p] * ma;
                    acck[p] = 0.f;
                }
                {
                    const unsigned (*bp)[4] = balw[(c & 1) ^ 1];
#pragma unroll
                    for (int r = 0; r < 4; r++) {
#pragma unroll
                        for (int ph = 0; ph < 4; ph++) {
                            unsigned bw = bp[r][ph];
                            unsigned st = ((bw >> sc) & 1u) | (((bw >> (16 + sc)) & 1u) << 1);
                            const float* kn = knib + (st * 256) * KSTR + sc;
                            int ue = 8 * r + 2 * ph;
#pragma unroll
                            for (int p = 0; p < 4; p++) {
                                int de = (8 * wid + 2 * p + half) + 31 - ue;
                                acck[p] += kn[de * KSTR];
                            }
                        }
                    }
                }
                float Qa = 0.f, Qb = 0.f;
                if (wid == 0) {
                    if (half == 0) ring[(c & 15) * SUB + sc] = 0u;
                } else {
                    PAIR_BAR(wid);
                    const unsigned (*bc)[4] = balw[c & 1];
#pragma unroll
                    for (int r = 0; r < 3; r++) if (r < wid) {
#pragma unroll
                        for (int ph = 0; ph < 4; ph++) {
                            unsigned bw = bc[r][ph];
                            int ue = 8 * r + 2 * ph;
                            float je = inj_sh[ue * SUB + sc];
                            float jo = inj_sh[(ue + 1) * SUB + sc];
                            Qa += powt[31 - ue] * je + powt[30 - ue] * jo;
                            Qb += wt[31 - ue] * je + wt[30 - ue] * jo;
                            unsigned st = ((bw >> sc) & 1u) | (((bw >> (16 + sc)) & 1u) << 1);
                            const float* kn = knib + (st * 256) * KSTR + sc;
#pragma unroll
                            for (int p = 0; p < 4; p++) {
                                int de = (8 * wid + 2 * p + half) - 1 - ue;
                                acck[p] += kn[de * KSTR];
                            }
                        }
                    }
                }
                // ---- 4 in-warp phases (8 steps), parallel hypothesis ballots ----
                unsigned balAv[4], balBv[4];
                float injE[4];
                float inw[4] = {0.f, 0.f, 0.f, 0.f};
#pragma unroll
                for (int p = 0; p < 4; p++) {
                    float sub = bPv[p] + acck[p] + inw[p] + rpw[p] * (ipm[p] * Qa + Qb);
                    unsigned b1 = __ballot_sync(0xFFFFFFFFu, sub > 0.f);
                    unsigned b2 = __ballot_sync(0xFFFFFFFFu, sub + kcr[0] > 0.f);
                    unsigned balA = b1 & 0xFFFFu;
                    unsigned h0 = b1 >> 16, h1 = b2 >> 16;
                    unsigned balB = (balA & h1) | (~balA & h0);
                    balAv[p] = balA; balBv[p] = balB;
                    float injEv = lut[0][balA & 15][sc] + lut[1][(balA >> 4) & 15][sc]
                                + lut[2][(balA >> 8) & 15][sc] + lut[3][(balA >> 12) & 15][sc];
                    float injOd = lut[0][balB & 15][sc] + lut[1][(balB >> 4) & 15][sc]
                                + lut[2][(balB >> 8) & 15][sc] + lut[3][(balB >> 12) & 15][sc];
                    injE[p] = half ? injOd : injEv;
                    if (p < 3) {
                        float fe = (float)((balA >> sc) & 1u);
                        float fo = (float)((balB >> sc) & 1u);
#pragma unroll
                        for (int pp = p + 1; pp < 4; pp++) {
                            const int bd = 2 * (pp - p) - 1;   // 1,3,5
                            float kA = half ? kcr[bd + 1] : kcr[bd];
                            float kB = half ? kcr[bd] : kcr[bd - 1];
                            float wA = half ? wtr[bd + 1] : wtr[bd];
                            float wB = half ? wtr[bd] : wtr[bd - 1];
                            inw[pp] += fe * kA + wA * injEv + fo * kB + wB * injOd;
                        }
                    }
                }
                // ---- publish + release ----
#pragma unroll
                for (int p = 0; p < 4; p++)
                    inj_sh[(8 * wid + 2 * p + half) * SUB + sc] = injE[p];
                if (lane == 0) {
                    balw[c & 1][wid][0] = balAv[0] | (balBv[0] << 16);
                    balw[c & 1][wid][1] = balAv[1] | (balBv[1] << 16);
                    balw[c & 1][wid][2] = balAv[2] | (balBv[2] << 16);
                    balw[c & 1][wid][3] = balAv[3] | (balBv[3] << 16);
                }
                PAIR_BAR(wid + 1);   // bars 1..4 (warp3 releases warp4 for epilogue)
                // ---- post-release ----
                if (half == 0) {
                    unsigned bits = 0u;
#pragma unroll
                    for (int p = 0; p < 4; p++)
                        bits |= (((balAv[p] >> sc) & 1u) << (8 * wid + 2 * p))
                              | (((balBv[p] >> sc) & 1u) << (8 * wid + 2 * p + 1));
                    atomicOr(&ring[(c & 15) * SUB + sc], bits);
                }
#pragma unroll
                for (int p = 0; p < 4; p++) {
                    unsigned myb = half ? balBv[p] : balAv[p];
                    spk_out[(t0 + 8 * wid + 2 * p + half) * SUB + sc] = ((myb >> sc) & 1u) ? 1.f : 0.f;
                }
                if (c + 1 < NCHUNK) {
#pragma unroll
                    for (int p = 0; p < 4; p++)
                        base_r[p] = g_base[(t0 + CHUNK + 8 * wid + 2 * p + half) * SUB + sc];
                }
            } else if (wid == 4) {
                // ---- epilogue warp: MA0/MB0 closed-form update (released by warp3) ----
                PAIR_BAR(4);
                int h = half, scl = sc;
                float sAp = 0.f, sBp = 0.f;
                int u0 = h * 16;
#pragma unroll
                for (int u = 0; u < 16; u++) {
                    float v = inj_sh[(u0 + u) * SUB + scl];
                    sAp += powt[31 - (u0 + u)] * v;
                    sBp += wt[31 - (u0 + u)] * v;
                }
                float sA = sAp + __shfl_xor_sync(0xFFFFFFFFu, sAp, 16);
                float sB = sBp + __shfl_xor_sync(0xFFFFFFFFu, sBp, 16);
                if (h == 0) {
                    float oMA = MA0[scl], oMB = MB0[scl];
                    MA0[scl] = p32 * oMA + sA;
                    MB0[scl] = p32 * oMB + 32.f * p32 * oMA + sB;
                }
            } else if (wid >= 8) {
                // ---- Pn warps: 3-way adaptive (ones-scan / zeros-scan / pair-LUT) ----
                if (c + 1 < NCHUNK) {
                    int wbase = c - 6;
#pragma unroll
                    for (int pass = 0; pass < 2; pass++) {
                        int s = pass ? pns1 : pns0;
                        unsigned W[6];
                        int ones = 0;
#pragma unroll
                        for (int q = 0; q < 6; q++) {
                            int w = wbase + q;
                            unsigned wd = (w >= 0) ? ring[(w & 15) * SUB + s] : 0u;
                            W[q] = wd;
                            ones += __popc(wd);
                        }
                        float Pv;
                        if (ones >= 168) {
                            float a0 = 0.f, a1 = 0.f;
#pragma unroll
                            for (int q = 0; q < 6; q++) {
                                unsigned zm = ~W[q];
                                int D0 = 223 - 32 * q + lane;
                                while (zm) {
                                    int b = __ffs(zm) - 1; zm &= zm - 1u;
                                    a0 += kpad[(D0 - b) * KSTR + s];
                                    if (zm) {
                                        b = __ffs(zm) - 1; zm &= zm - 1u;
                                        a1 += kpad[(D0 - b) * KSTR + s];
                                    }
                                }
                            }
                            Pv = S2_sh[lane * KSTR + s] - a0 - a1;
                        } else if (ones <= 24) {
                            float a0 = 0.f, a1 = 0.f;
#pragma unroll
                            for (int q = 0; q < 6; q++) {
                                unsigned om = W[q];
                                int D0 = 223 - 32 * q + lane;
                                while (om) {
                                    int b = __ffs(om) - 1; om &= om - 1u;
                                    a0 += kpad[(D0 - b) * KSTR + s];
                                    if (om) {
                                        b = __ffs(om) - 1; om &= om - 1u;
                                        a1 += kpad[(D0 - b) * KSTR + s];
                                    }
                                }
                            }
                            Pv = a0 + a1;
                        } else {
                            float a0 = 0.f, a1 = 0.f;
#pragma unroll
                            for (int q = 0; q < 6; q++) {
                                unsigned Wq = W[q];
                                int D0 = 223 - 32 * q + lane;
#pragma unroll
                                for (int jp = 0; jp < 16; jp += 2) {
                                    unsigned st0 = (Wq >> (2 * jp)) & 3u;
                                    unsigned st1 = (Wq >> (2 * jp + 2)) & 3u;
                                    if (st0) a0 += knib[(st0 * 256 + (D0 - 2 * jp)) * KSTR + s];
                                    if (st1) a1 += knib[(st1 * 256 + (D0 - 2 * jp - 2)) * KSTR + s];
                                }
                            }
                            Pv = a0 + a1;
                        }
                        Pn_sh[(c + 1) & 1][lane * KSTR + s] = Pv;
                    }
                }
            }
            __syncthreads();
        } else {
            // ---- general fallback: per-thread pre-phase + serial loop ----
            float P = 0.f;
            {
                int t = t0 + fi;
                int uhi = t0 - 1;
                int ulo = t - TNO; if (ulo < 0) ulo = 0;
                if (uhi >= ulo) {
                    int wlo = ulo >> 5;
#pragma unroll
                    for (int q8 = 0; q8 < 8; q8++) {
                        int w = wlo + q8;
                        int bu = w << 5;
                        unsigned valid = 0u;
                        if (bu >= 0 && bu <= uhi) {
                            valid = 0xFFFFFFFFu;
                            if (bu < ulo) valid <<= (ulo - bu);
                            int hb = uhi - bu;
                            if (hb < 31) valid &= ((2u << hb) - 1u);
                        }
                        unsigned om = (valid ? ring[(w & 15) * SUB + fs] : 0u) & valid;
                        int Cw = t - 1 - (w << 5);
                        while (om) {
                            int b = __ffs(om) - 1; om &= om - 1u;
                            P += kpad[(Cw - b) * KSTR + fs];
                        }
                    }
                }
            }
            P_sh[tid] = P;
            base_sh[tid] = fbase;
            __syncthreads();
            if (tid < 16) {
                int ss = tid;
                unsigned myhist = 0u;
                float rho_s = rho_sh[ss];
                for (int ii = 0; ii < CHUNK; ii++) {
                    float Pv2 = P_sh[ii * SUB + ss];
                    float bv = base_sh[ii * SUB + ss];
                    unsigned m = ii ? ((1u << ii) - 1u) : 0u;
                    unsigned om = myhist & m;
                    float intra;
                    if (2 * __popc(om) > ii) {
                        unsigned zm = om ^ m;
                        float a = 0.f;
                        while (zm) { int b = __ffs(zm) - 1; zm &= zm - 1u; a += kpad[b * KSTR + ss]; }
                        intra = Kpre_sh[ii * KSTR + ss] - a;
                    } else {
                        float a = 0.f;
                        while (om) { int b = __ffs(om) - 1; om &= om - 1u; a += kpad[b * KSTR + ss]; }
                        intra = a;
                    }
                    float sub = bv + Pv2 + intra + MBr;
                    bool sp = sub > 0.f;
                    spf[ii * SUB + ss] = sp ? 1.f : 0.f;
                    myhist = (myhist << 1) | (sp ? 1u : 0u);
                    float Ao = A;
                    B = rho_s * (B + Ao);
                    A = rho_s * Ao + (sp ? 1.f : 0.f);
                    float accv = 0.f;
#pragma unroll
                    for (int q = 0; q < 16; q++)
                        accv += cwrow[q] * __shfl_sync(0x0000FFFFu, B, q);
                    MBr = accv;
                }
                ring[((t0 >> 5) & 15) * SUB + ss] = __brev(myhist);
            }
            __syncthreads();
            spk_out[t0 * SUB + tid] = spf[tid];
            float nextbase = 0.f;
            if (c + 1 < NCHUNK) nextbase = g_base[(t0 + CHUNK + fi) * SUB + fs];
            __syncthreads();
            fbase = nextbase;
        }
    }
}

// ---------------- launch ----------------
extern "C" void kernel_launch(void* const* d_in, const int* in_sizes, int n_in,
                              void* d_out, int out_size)
{
    const float* S_e     = (const float*)d_in[0];
    const float* S_i     = (const float*)d_in[1];
    const float* C_den   = (const float*)d_in[2];
    const float* C_syn_e = (const float*)d_in[3];
    const float* C_syn_i = (const float*)d_in[4];
    const float* Tau_e   = (const float*)d_in[5];
    const float* Tau_i   = (const float*)d_in[6];
    const float* W_e     = (const float*)d_in[7];
    const float* W_i     = (const float*)d_in[8];
    const float* D_e     = (const float*)d_in[9];
    const float* D_i     = (const float*)d_in[10];
    const float* Tau_spk = (const float*)d_in[11];
    const float* W_spk   = (const float*)d_in[12];
    const float* W_hist  = (const float*)d_in[13];
    const float* Theta   = (const float*)d_in[14];
    float* out = (float*)d_out;
    float* out_filters = out + T_DATA * SUB;

    cudaFuncSetAttribute(k_scan, cudaFuncAttributeMaxDynamicSharedMemorySize, KNIB_BYTES);

    k_setup<<<1, 256>>>(C_den, C_syn_e, C_syn_i, Tau_e, Tau_i, W_e, W_i,
                        D_e, D_i, Tau_spk, W_spk, W_hist, out_filters);
    k_segsum<<<T_DATA / SEG_ROWS, 256>>>(S_e, S_i);
    k_conv<<<(T_DATA + TILE_T - 1) / TILE_T, 256>>>(Theta);
    k_scan<<<1, 512, KNIB_BYTES>>>(out);
}